// round 7
// baseline (speedup 1.0000x reference)
#include <cuda_runtime.h>
#include <cstdint>
#include <math.h>

// SelfAttention B=8, C=64, N=4096 fp32. v4: fp16 m16n8k16 + ldmatrix, with
// half-tile software pipelining so MUFU (exp) overlaps the tensor pipe:
//   G1(mp0-1) -> exp(s0..3) -> G1(mp2-3) -> G2(kk0-1) -> exp(s4..7) -> G2(kk2-3)
// Layouts/addressing identical to R6 (verified, rel_err 4.3e-4).

#define NSEQ 4096
#define CD   64
#define BTM  64
#define NTIL (NSEQ / BTM)     // 64

#define SQB   272             // fp32 stage row stride (68 floats)
#define OQ0   0               // stage buf0: Q 64x272=17408, V at +17408
#define OQ1   34816           // stage buf1
#define STGV  17408
#define OFF_KS 69632          // fp16 K [c=64][n=128], stride 272B
#define KSB    272
#define OFF_QF 87040          // fp16 Q [c=64][m=64], stride 144B
#define OFF_VF 96256          // fp16 V [c=64][m=64], stride 144B
#define QFB    144
#define SMEM_TOTAL 105472
#define OSTB   544            // epilogue O staging stride (at offset 0)

static __device__ __forceinline__ uint32_t smem_u32(const void* p) {
    uint32_t a;
    asm("{ .reg .u64 t; cvta.to.shared.u64 t, %1; cvt.u32.u64 %0, t; }" : "=r"(a) : "l"(p));
    return a;
}
static __device__ __forceinline__ float ex2f(float x) {
    float r; asm("ex2.approx.f32 %0, %1;" : "=f"(r) : "f"(x)); return r;
}
static __device__ __forceinline__ uint32_t pkh2(float lo, float hi) {
    uint32_t d;
    asm("cvt.rn.f16x2.f32 %0, %1, %2;" : "=r"(d) : "f"(hi), "f"(lo));
    return d;
}

#define CP16(dst, src) asm volatile("cp.async.cg.shared.global [%0], [%1], 16;" :: "r"(dst), "l"(src) : "memory")
#define CP_COMMIT()    asm volatile("cp.async.commit_group;" ::: "memory")
#define CP_WAIT0()     asm volatile("cp.async.wait_group 0;" ::: "memory")

#define LDSM4(r0,r1,r2,r3,a) \
    asm volatile("ldmatrix.sync.aligned.m8n8.x4.shared.b16 {%0,%1,%2,%3}, [%4];" \
        : "=r"(r0),"=r"(r1),"=r"(r2),"=r"(r3) : "r"(a))
#define LDSM4T(r0,r1,r2,r3,a) \
    asm volatile("ldmatrix.sync.aligned.m8n8.x4.trans.shared.b16 {%0,%1,%2,%3}, [%4];" \
        : "=r"(r0),"=r"(r1),"=r"(r2),"=r"(r3) : "r"(a))

#define MMA16(d, a0, a1, a2, a3, b0, b1)                                         \
    asm volatile("mma.sync.aligned.m16n8k16.row.col.f32.f16.f16.f32 "            \
        "{%0,%1,%2,%3}, {%4,%5,%6,%7}, {%8,%9}, {%0,%1,%2,%3};"                  \
        : "+f"((d)[0]), "+f"((d)[1]), "+f"((d)[2]), "+f"((d)[3])                 \
        : "r"(a0), "r"(a1), "r"(a2), "r"(a3), "r"(b0), "r"(b1))

static __device__ __forceinline__ void cvt_qv(char* smem, uint32_t stg, uint32_t dst, int tid) {
    const int c = tid & 63, q = tid >> 6;
    const char* src = smem + stg + c * SQB + q * 64;
    char* d = smem + dst + c * QFB + q * 32;
    uint32_t h[8];
    #pragma unroll
    for (int i = 0; i < 4; ++i) {
        float4 v = *(const float4*)(src + i * 16);
        h[2 * i]     = pkh2(v.x, v.y);
        h[2 * i + 1] = pkh2(v.z, v.w);
    }
    *(uint4*)(d)      = make_uint4(h[0], h[1], h[2], h[3]);
    *(uint4*)(d + 16) = make_uint4(h[4], h[5], h[6], h[7]);
}

__global__ __launch_bounds__(256, 2)
void attn_mma_v4(const float* __restrict__ K, const float* __restrict__ Q,
                 const float* __restrict__ V, float* __restrict__ Out)
{
    extern __shared__ char smem[];
    const uint32_t sb = smem_u32(smem);
    const int tid  = threadIdx.x;
    const int wid  = tid >> 5, lane = tid & 31;
    const int g    = lane >> 2, tig = lane & 3;
    const int nw0  = wid * 16;
    const int b    = blockIdx.y, n0 = blockIdx.x * 128;
    const size_t base = (size_t)b * CD * NSEQ;
    const float* kb = K + base;
    const float* qb = Q + base;
    const float* vb = V + base;

    const int cc = tid >> 2, jj = tid & 3;

    // ---- prologue: K fp32 -> XOR-swizzled stage spanning both bufs ----
    #pragma unroll
    for (int i = 0; i < 8; ++i) {
        int j = jj + 4 * i;
        uint32_t dst = sb + cc * 512 + ((j * 16) ^ ((cc & 7) * 16));
        CP16(dst, kb + (size_t)cc * NSEQ + n0 + j * 4);
    }
    CP_COMMIT(); CP_WAIT0();
    __syncthreads();
    {   // K -> fp16 [c][n], stride KSB
        const int c = tid & 63, q = tid >> 6;
        #pragma unroll
        for (int ii = 0; ii < 4; ++ii) {
            uint32_t h[4];
            #pragma unroll
            for (int k2 = 0; k2 < 2; ++k2) {
                int i = 2 * ii + k2;
                float4 v = *(const float4*)(smem + c * 512 + ((q * 128 + i * 16) ^ ((c & 7) * 16)));
                h[2 * k2]     = pkh2(v.x, v.y);
                h[2 * k2 + 1] = pkh2(v.z, v.w);
            }
            *(uint4*)(smem + OFF_KS + c * KSB + q * 64 + ii * 16) = make_uint4(h[0], h[1], h[2], h[3]);
        }
    }
    __syncthreads();
    // tile 0 Q/V -> stage buf0
    #pragma unroll
    for (int i = 0; i < 4; ++i) {
        int j = jj + 4 * i;
        CP16(sb + OQ0 + cc * SQB + j * 16, qb + (size_t)cc * NSEQ + j * 4);
        CP16(sb + OQ0 + STGV + cc * SQB + j * 16, vb + (size_t)cc * NSEQ + j * 4);
    }
    CP_COMMIT();

    float o[8][4];
    float rs0 = 0.f, rs1 = 0.f;
    #pragma unroll
    for (int oc = 0; oc < 8; ++oc)
        #pragma unroll
        for (int e = 0; e < 4; ++e) o[oc][e] = 0.f;

    const uint32_t kaddr = sb + OFF_KS + ((lane & 7) + ((lane & 16) ? 8 : 0)) * KSB
                         + (nw0 + ((lane & 8) ? 8 : 0)) * 2;
    const uint32_t qaddr = sb + OFF_QF + ((lane & 7) + ((lane & 8) ? 8 : 0)) * QFB
                         + ((lane & 16) ? 16 : 0);
    const uint32_t vaddr = sb + OFF_VF + ((lane & 7) + ((lane & 16) ? 8 : 0)) * QFB
                         + ((lane & 8) ? 16 : 0);

    for (int t = 0; t < NTIL; ++t) {
        const uint32_t stg = (t & 1) ? OQ1 : OQ0;

        CP_WAIT0();
        __syncthreads();
        cvt_qv(smem, stg, OFF_QF, tid);
        cvt_qv(smem, stg + STGV, OFF_VF, tid);
        __syncthreads();

        if (t + 1 < NTIL) {
            const uint32_t so = (t & 1) ? OQ0 : OQ1;
            const float* qs = qb + (size_t)(t + 1) * BTM;
            const float* vs = vb + (size_t)(t + 1) * BTM;
            #pragma unroll
            for (int i = 0; i < 4; ++i) {
                int j = jj + 4 * i;
                CP16(sb + so + cc * SQB + j * 16, qs + (size_t)cc * NSEQ + j * 4);
                CP16(sb + so + STGV + cc * SQB + j * 16, vs + (size_t)cc * NSEQ + j * 4);
            }
            CP_COMMIT();
        }

        float s[8][4];
        #pragma unroll
        for (int mt = 0; mt < 8; ++mt)
            #pragma unroll
            for (int e = 0; e < 4; ++e) s[mt][e] = 0.f;

        // K fragments for the whole tile (4 k16 steps), hoisted
        uint32_t ak[4][4];
        #pragma unroll
        for (int kk = 0; kk < 4; ++kk)
            LDSM4T(ak[kk][0], ak[kk][1], ak[kk][2], ak[kk][3], kaddr + kk * 16 * KSB);

        // ---- GEMM1 half A: mp = 0,1 -> s[0..3] ----
        #pragma unroll
        for (int mp = 0; mp < 2; ++mp)
            #pragma unroll
            for (int kk = 0; kk < 4; ++kk) {
                uint32_t b0, b1, b2, b3;
                LDSM4T(b0, b1, b2, b3, qaddr + kk * 16 * QFB + mp * 32);
                MMA16(s[2 * mp],     ak[kk][0], ak[kk][1], ak[kk][2], ak[kk][3], b0, b1);
                MMA16(s[2 * mp + 1], ak[kk][0], ak[kk][1], ak[kk][2], ak[kk][3], b2, b3);
            }

        // ---- exp half A (MUFU; independent of GEMM1 half B below) ----
        #pragma unroll
        for (int mt = 0; mt < 4; ++mt)
            #pragma unroll
            for (int e = 0; e < 4; ++e) {
                float p = ex2f(s[mt][e] * 0.1803368801f);   // 0.125*log2(e)
                s[mt][e] = p;
                if (e < 2) rs0 += p; else rs1 += p;
            }

        // ---- GEMM1 half B: mp = 2,3 -> s[4..7] ----
        #pragma unroll
        for (int mp = 2; mp < 4; ++mp)
            #pragma unroll
            for (int kk = 0; kk < 4; ++kk) {
                uint32_t b0, b1, b2, b3;
                LDSM4T(b0, b1, b2, b3, qaddr + kk * 16 * QFB + mp * 32);
                MMA16(s[2 * mp],     ak[kk][0], ak[kk][1], ak[kk][2], ak[kk][3], b0, b1);
                MMA16(s[2 * mp + 1], ak[kk][0], ak[kk][1], ak[kk][2], ak[kk][3], b2, b3);
            }

        // ---- GEMM2 half A: kk = 0,1 (consumes P[0..3]) ----
        #pragma unroll
        for (int kk = 0; kk < 2; ++kk) {
            uint32_t a0 = pkh2(s[2 * kk][0],     s[2 * kk][1]);
            uint32_t a1 = pkh2(s[2 * kk][2],     s[2 * kk][3]);
            uint32_t a2 = pkh2(s[2 * kk + 1][0], s[2 * kk + 1][1]);
            uint32_t a3 = pkh2(s[2 * kk + 1][2], s[2 * kk + 1][3]);
            #pragma unroll
            for (int ct = 0; ct < 4; ++ct) {
                uint32_t b0, b1, b2, b3;
                LDSM4(b0, b1, b2, b3, vaddr + ct * 16 * QFB + kk * 32);
                MMA16(o[2 * ct],     a0, a1, a2, a3, b0, b1);
                MMA16(o[2 * ct + 1], a0, a1, a2, a3, b2, b3);
            }
        }

        // ---- exp half B (overlaps GEMM2 half A issue-wise) ----
        #pragma unroll
        for (int mt = 4; mt < 8; ++mt)
            #pragma unroll
            for (int e = 0; e < 4; ++e) {
                float p = ex2f(s[mt][e] * 0.1803368801f);
                s[mt][e] = p;
                if (e < 2) rs0 += p; else rs1 += p;
            }

        // ---- GEMM2 half B: kk = 2,3 ----
        #pragma unroll
        for (int kk = 2; kk < 4; ++kk) {
            uint32_t a0 = pkh2(s[2 * kk][0],     s[2 * kk][1]);
            uint32_t a1 = pkh2(s[2 * kk][2],     s[2 * kk][3]);
            uint32_t a2 = pkh2(s[2 * kk + 1][0], s[2 * kk + 1][1]);
            uint32_t a3 = pkh2(s[2 * kk + 1][2], s[2 * kk + 1][3]);
            #pragma unroll
            for (int ct = 0; ct < 4; ++ct) {
                uint32_t b0, b1, b2, b3;
                LDSM4(b0, b1, b2, b3, vaddr + ct * 16 * QFB + kk * 32);
                MMA16(o[2 * ct],     a0, a1, a2, a3, b0, b1);
                MMA16(o[2 * ct + 1], a0, a1, a2, a3, b2, b3);
            }
        }
    }

    // ---- rowsums across the 4 tig lanes ----
    rs0 += __shfl_xor_sync(0xffffffffu, rs0, 1);
    rs0 += __shfl_xor_sync(0xffffffffu, rs0, 2);
    rs1 += __shfl_xor_sync(0xffffffffu, rs1, 1);
    rs1 += __shfl_xor_sync(0xffffffffu, rs1, 2);
    const float inv0 = 1.f / rs0;
    const float inv1 = 1.f / rs1;

    __syncthreads();   // stage region free -> O staging [c=64][n=128]

    #pragma unroll
    for (int oc = 0; oc < 8; ++oc)
        #pragma unroll
        for (int e = 0; e < 4; ++e) {
            int c = 8 * oc + 2 * tig + (e & 1);
            int n = nw0 + g + 8 * (e >> 1);
            *(float*)(smem + c * OSTB + n * 4) = o[oc][e] * ((e < 2) ? inv0 : inv1);
        }
    __syncthreads();

    #pragma unroll
    for (int i = 0; i < 32; ++i) {
        int flat = i * 256 + tid;
        int c = flat >> 7, n = flat & 127;
        Out[base + (size_t)c * NSEQ + n0 + n] = *(const float*)(smem + c * OSTB + n * 4);
    }
}

extern "C" void kernel_launch(void* const* d_in, const int* in_sizes, int n_in,
                              void* d_out, int out_size)
{
    const float* k = (const float*)d_in[0];
    const float* q = (const float*)d_in[1];
    const float* v = (const float*)d_in[2];
    float* out = (float*)d_out;

    cudaFuncSetAttribute(attn_mma_v4, cudaFuncAttributeMaxDynamicSharedMemorySize, SMEM_TOTAL);
    dim3 grid(NSEQ / 128, 8);   // 256 CTAs, 2 per SM
    attn_mma_v4<<<grid, 256, SMEM_TOTAL>>>(k, q, v, out);
}

// round 8
// speedup vs baseline: 1.3534x; 1.3534x over previous
#include <cuda_runtime.h>
#include <cuda_fp16.h>
#include <cstdint>
#include <math.h>

// SelfAttention B=8, C=64, N=4096 fp32. v5:
//  kernel 1: K,Q,V fp32 -> fp16 device-global arrays (one-time, ~37MB traffic)
//  kernel 2: flash attention, fp16 m16n8k16 mma.sync + ldmatrix, direct fp16
//            cp.async (no per-tile cvt phase), 128-m tiles with two 64-m halves,
//            ONE barrier per 128-m tile. Addressing identical to R6 (verified).

#define NSEQ 4096
#define CD   64
#define TOT  (8 * CD * NSEQ)   // 2097152 elems per tensor

#define STR  272               // universal fp16 smem row stride (256B data + 16 pad)
#define OFF_KS 0               // K  [c=64][n=128] fp16, 17408 B
#define OFF_Q0 17408           // Q  [c=64][m=128] fp16, double buffered
#define OFF_Q1 34816
#define OFF_V0 52224           // V  [c=64][m=128] fp16, double buffered
#define OFF_V1 69632
#define SMEM_TOTAL 87040
#define OSTB 544               // epilogue fp32 O staging stride (offset 0)

__device__ __align__(16) __half gK[TOT];
__device__ __align__(16) __half gQ[TOT];
__device__ __align__(16) __half gV[TOT];

static __device__ __forceinline__ uint32_t smem_u32(const void* p) {
    uint32_t a;
    asm("{ .reg .u64 t; cvta.to.shared.u64 t, %1; cvt.u32.u64 %0, t; }" : "=r"(a) : "l"(p));
    return a;
}
static __device__ __forceinline__ float ex2f(float x) {
    float r; asm("ex2.approx.f32 %0, %1;" : "=f"(r) : "f"(x)); return r;
}
static __device__ __forceinline__ uint32_t pkh2(float lo, float hi) {
    uint32_t d;
    asm("cvt.rn.f16x2.f32 %0, %1, %2;" : "=r"(d) : "f"(hi), "f"(lo));
    return d;
}

#define CP16(dst, src) asm volatile("cp.async.cg.shared.global [%0], [%1], 16;" :: "r"(dst), "l"(src) : "memory")
#define CP_COMMIT()    asm volatile("cp.async.commit_group;" ::: "memory")
#define CP_WAIT0()     asm volatile("cp.async.wait_group 0;" ::: "memory")

#define LDSM4(r0,r1,r2,r3,a) \
    asm volatile("ldmatrix.sync.aligned.m8n8.x4.shared.b16 {%0,%1,%2,%3}, [%4];" \
        : "=r"(r0),"=r"(r1),"=r"(r2),"=r"(r3) : "r"(a))
#define LDSM4T(r0,r1,r2,r3,a) \
    asm volatile("ldmatrix.sync.aligned.m8n8.x4.trans.shared.b16 {%0,%1,%2,%3}, [%4];" \
        : "=r"(r0),"=r"(r1),"=r"(r2),"=r"(r3) : "r"(a))

#define MMA16(d, a0, a1, a2, a3, b0, b1)                                         \
    asm volatile("mma.sync.aligned.m16n8k16.row.col.f32.f16.f16.f32 "            \
        "{%0,%1,%2,%3}, {%4,%5,%6,%7}, {%8,%9}, {%0,%1,%2,%3};"                  \
        : "+f"((d)[0]), "+f"((d)[1]), "+f"((d)[2]), "+f"((d)[3])                 \
        : "r"(a0), "r"(a1), "r"(a2), "r"(a3), "r"(b0), "r"(b1))

// ---- kernel 1: fp32 -> fp16 ----
__global__ __launch_bounds__(256)
void cvt_to_f16(const float* __restrict__ K, const float* __restrict__ Q,
                const float* __restrict__ V)
{
    const int i = (blockIdx.x * 256 + threadIdx.x) * 8;
    const float* src = (blockIdx.y == 0) ? K : (blockIdx.y == 1) ? Q : V;
    __half* dst = (blockIdx.y == 0) ? gK : (blockIdx.y == 1) ? gQ : gV;
    float4 a = *(const float4*)(src + i);
    float4 b = *(const float4*)(src + i + 4);
    *(uint4*)(dst + i) = make_uint4(pkh2(a.x, a.y), pkh2(a.z, a.w),
                                    pkh2(b.x, b.y), pkh2(b.z, b.w));
}

// ---- kernel 2: attention ----
__global__ __launch_bounds__(256, 2)
void attn_mma_v5(float* __restrict__ Out)
{
    extern __shared__ char smem[];
    const uint32_t sb = smem_u32(smem);
    const int tid  = threadIdx.x;
    const int wid  = tid >> 5, lane = tid & 31;
    const int g    = lane >> 2, tig = lane & 3;
    const int nw0  = wid * 16;
    const int b    = blockIdx.y, n0 = blockIdx.x * 128;
    const size_t base = (size_t)b * CD * NSEQ;
    const __half* kh = gK + base;
    const __half* qh = gQ + base;
    const __half* vh = gV + base;

    const int cc = tid >> 4, jc = tid & 15;   // loader: 16 rows/pass, 16 chunks/row

    // ---- prologue: K tile + tile 0 of Q/V (fp16, direct) ----
    #pragma unroll
    for (int i = 0; i < 4; ++i) {
        int c = cc + i * 16;
        CP16(sb + OFF_KS + c * STR + jc * 16, kh + (size_t)c * NSEQ + n0 + jc * 8);
        CP16(sb + OFF_Q0 + c * STR + jc * 16, qh + (size_t)c * NSEQ + jc * 8);
        CP16(sb + OFF_V0 + c * STR + jc * 16, vh + (size_t)c * NSEQ + jc * 8);
    }
    CP_COMMIT();

    float o[8][4];
    float rs0 = 0.f, rs1 = 0.f;
    #pragma unroll
    for (int oc = 0; oc < 8; ++oc)
        #pragma unroll
        for (int e = 0; e < 4; ++e) o[oc][e] = 0.f;

    // ldmatrix lane base addresses (R6-verified mapping, stride 272B)
    const uint32_t kaddr = sb + OFF_KS + ((lane & 7) + ((lane & 16) ? 8 : 0)) * STR
                         + (nw0 + ((lane & 8) ? 8 : 0)) * 2;
    const uint32_t qbase = ((lane & 7) + ((lane & 8) ? 8 : 0)) * STR
                         + ((lane & 16) ? 16 : 0);
    const uint32_t vbase = ((lane & 7) + ((lane & 16) ? 8 : 0)) * STR
                         + ((lane & 8) ? 16 : 0);

    CP_WAIT0();
    __syncthreads();

    // K fragments: constant across ALL tiles — load once
    uint32_t ak[4][4];
    #pragma unroll
    for (int kk = 0; kk < 4; ++kk)
        LDSM4T(ak[kk][0], ak[kk][1], ak[kk][2], ak[kk][3], kaddr + kk * 16 * STR);

    for (int t = 0; t < 32; ++t) {                 // 32 tiles of 128 m
        const uint32_t qs = sb + ((t & 1) ? OFF_Q1 : OFF_Q0);
        const uint32_t vs = sb + ((t & 1) ? OFF_V1 : OFF_V0);

        if (t > 0) { CP_WAIT0(); __syncthreads(); }  // tile t ready; buf (t+1)&1 free

        if (t + 1 < 32) {                           // prefetch tile t+1
            const uint32_t qo = (t & 1) ? OFF_Q0 : OFF_Q1;
            const uint32_t vo = (t & 1) ? OFF_V0 : OFF_V1;
            const __half* qsrc = qh + (size_t)(t + 1) * 128;
            const __half* vsrc = vh + (size_t)(t + 1) * 128;
            #pragma unroll
            for (int i = 0; i < 4; ++i) {
                int c = cc + i * 16;
                CP16(sb + qo + c * STR + jc * 16, qsrc + (size_t)c * NSEQ + jc * 8);
                CP16(sb + vo + c * STR + jc * 16, vsrc + (size_t)c * NSEQ + jc * 8);
            }
            CP_COMMIT();
        }

        #pragma unroll
        for (int h = 0; h < 2; ++h) {               // two 64-m halves
            const uint32_t hoff = h * 128;          // 64 m * 2B

            // ---- GEMM1: S[16n][64m] = K^T x Q ----
            float s[8][4];
            #pragma unroll
            for (int mt = 0; mt < 8; ++mt)
                #pragma unroll
                for (int e = 0; e < 4; ++e) s[mt][e] = 0.f;

            #pragma unroll
            for (int mp = 0; mp < 4; ++mp)
                #pragma unroll
                for (int kk = 0; kk < 4; ++kk) {
                    uint32_t b0, b1, b2, b3;
                    LDSM4T(b0, b1, b2, b3, qs + qbase + kk * 16 * STR + hoff + mp * 32);
                    MMA16(s[2 * mp],     ak[kk][0], ak[kk][1], ak[kk][2], ak[kk][3], b0, b1);
                    MMA16(s[2 * mp + 1], ak[kk][0], ak[kk][1], ak[kk][2], ak[kk][3], b2, b3);
                }

            // ---- P = exp(S/8); fp32 rowsum ----
            #pragma unroll
            for (int mt = 0; mt < 8; ++mt)
                #pragma unroll
                for (int e = 0; e < 4; ++e) {
                    float p = ex2f(s[mt][e] * 0.1803368801f);   // 0.125*log2(e)
                    s[mt][e] = p;
                    if (e < 2) rs0 += p; else rs1 += p;
                }

            // ---- GEMM2: O[16n][64c] += P x V^T ----
            #pragma unroll
            for (int kk = 0; kk < 4; ++kk) {
                uint32_t a0 = pkh2(s[2 * kk][0],     s[2 * kk][1]);
                uint32_t a1 = pkh2(s[2 * kk][2],     s[2 * kk][3]);
                uint32_t a2 = pkh2(s[2 * kk + 1][0], s[2 * kk + 1][1]);
                uint32_t a3 = pkh2(s[2 * kk + 1][2], s[2 * kk + 1][3]);
                #pragma unroll
                for (int ct = 0; ct < 4; ++ct) {
                    uint32_t b0, b1, b2, b3;
                    LDSM4(b0, b1, b2, b3, vs + vbase + ct * 16 * STR + hoff + kk * 32);
                    MMA16(o[2 * ct],     a0, a1, a2, a3, b0, b1);
                    MMA16(o[2 * ct + 1], a0, a1, a2, a3, b2, b3);
                }
            }
        }
    }

    // ---- rowsums across the 4 tig lanes ----
    rs0 += __shfl_xor_sync(0xffffffffu, rs0, 1);
    rs0 += __shfl_xor_sync(0xffffffffu, rs0, 2);
    rs1 += __shfl_xor_sync(0xffffffffu, rs1, 1);
    rs1 += __shfl_xor_sync(0xffffffffu, rs1, 2);
    const float inv0 = 1.f / rs0;
    const float inv1 = 1.f / rs1;

    __syncthreads();   // all reads of smem tiles done -> reuse as O staging

    #pragma unroll
    for (int oc = 0; oc < 8; ++oc)
        #pragma unroll
        for (int e = 0; e < 4; ++e) {
            int c = 8 * oc + 2 * tig + (e & 1);
            int n = nw0 + g + 8 * (e >> 1);
            *(float*)(smem + c * OSTB + n * 4) = o[oc][e] * ((e < 2) ? inv0 : inv1);
        }
    __syncthreads();

    #pragma unroll
    for (int i = 0; i < 32; ++i) {
        int flat = i * 256 + tid;
        int c = flat >> 7, n = flat & 127;
        Out[base + (size_t)c * NSEQ + n0 + n] = *(const float*)(smem + c * OSTB + n * 4);
    }
}

extern "C" void kernel_launch(void* const* d_in, const int* in_sizes, int n_in,
                              void* d_out, int out_size)
{
    const float* k = (const float*)d_in[0];
    const float* q = (const float*)d_in[1];
    const float* v = (const float*)d_in[2];
    float* out = (float*)d_out;

    dim3 gcvt(TOT / (256 * 8), 3);     // 1024 x 3
    cvt_to_f16<<<gcvt, 256>>>(k, q, v);

    cudaFuncSetAttribute(attn_mma_v5, cudaFuncAttributeMaxDynamicSharedMemorySize, SMEM_TOTAL);
    dim3 grid(NSEQ / 128, 8);          // 256 CTAs, 2 per SM
    attn_mma_v5<<<grid, 256, SMEM_TOTAL>>>(out);
}

// round 9
// speedup vs baseline: 1.5118x; 1.1171x over previous
#include <cuda_runtime.h>
#include <cuda_fp16.h>
#include <cstdint>
#include <math.h>

// SelfAttention B=8, C=64, N=4096 fp32. v6:
//  kernel 1: K,Q,V fp32 -> fp16 globals; K pre-scaled by 0.125*log2(e) so
//            GEMM1 yields log2-domain scores directly.
//  kernel 2: flash attention, fp16 m16n8k16 + ldmatrix (R6-verified layout).
//            Softmax: pack S pairs (pkh2) -> ex2.approx.f16x2 (16 MUFU/half).
//            Rowsum: extra MMA with B = ones -> denominator == exact sum of the
//            fp16 P the numerator uses; no FADD chain, no shfl reduction.

#define NSEQ 4096
#define CD   64
#define TOT  (8 * CD * NSEQ)

#define STR  272               // fp16 smem row stride (256B data + 16 pad)
#define OFF_KS 0
#define OFF_Q0 17408
#define OFF_Q1 34816
#define OFF_V0 52224
#define OFF_V1 69632
#define SMEM_TOTAL 87040
#define OSTB 544               // epilogue fp32 O staging stride (offset 0)

#define ONES2 0x3C003C00u      // f16x2 {1.0, 1.0}

__device__ __align__(16) __half gK[TOT];
__device__ __align__(16) __half gQ[TOT];
__device__ __align__(16) __half gV[TOT];

static __device__ __forceinline__ uint32_t smem_u32(const void* p) {
    uint32_t a;
    asm("{ .reg .u64 t; cvta.to.shared.u64 t, %1; cvt.u32.u64 %0, t; }" : "=r"(a) : "l"(p));
    return a;
}
static __device__ __forceinline__ uint32_t pkh2(float lo, float hi) {
    uint32_t d;
    asm("cvt.rn.f16x2.f32 %0, %1, %2;" : "=r"(d) : "f"(hi), "f"(lo));
    return d;
}
static __device__ __forceinline__ uint32_t ex2h2(uint32_t x) {
    uint32_t d;
    asm("ex2.approx.f16x2 %0, %1;" : "=r"(d) : "r"(x));
    return d;
}

#define CP16(dst, src) asm volatile("cp.async.cg.shared.global [%0], [%1], 16;" :: "r"(dst), "l"(src) : "memory")
#define CP_COMMIT()    asm volatile("cp.async.commit_group;" ::: "memory")
#define CP_WAIT0()     asm volatile("cp.async.wait_group 0;" ::: "memory")

#define LDSM4(r0,r1,r2,r3,a) \
    asm volatile("ldmatrix.sync.aligned.m8n8.x4.shared.b16 {%0,%1,%2,%3}, [%4];" \
        : "=r"(r0),"=r"(r1),"=r"(r2),"=r"(r3) : "r"(a))
#define LDSM4T(r0,r1,r2,r3,a) \
    asm volatile("ldmatrix.sync.aligned.m8n8.x4.trans.shared.b16 {%0,%1,%2,%3}, [%4];" \
        : "=r"(r0),"=r"(r1),"=r"(r2),"=r"(r3) : "r"(a))

#define MMA16(d, a0, a1, a2, a3, b0, b1)                                         \
    asm volatile("mma.sync.aligned.m16n8k16.row.col.f32.f16.f16.f32 "            \
        "{%0,%1,%2,%3}, {%4,%5,%6,%7}, {%8,%9}, {%0,%1,%2,%3};"                  \
        : "+f"((d)[0]), "+f"((d)[1]), "+f"((d)[2]), "+f"((d)[3])                 \
        : "r"(a0), "r"(a1), "r"(a2), "r"(a3), "r"(b0), "r"(b1))

// ---- kernel 1: fp32 -> fp16 (K pre-scaled by 0.125*log2 e) ----
__global__ __launch_bounds__(256)
void cvt_to_f16(const float* __restrict__ K, const float* __restrict__ Q,
                const float* __restrict__ V)
{
    const int i = (blockIdx.x * 256 + threadIdx.x) * 8;
    const float sc = (blockIdx.y == 0) ? 0.18033688011112042f : 1.0f;
    const float* src = (blockIdx.y == 0) ? K : (blockIdx.y == 1) ? Q : V;
    __half* dst = (blockIdx.y == 0) ? gK : (blockIdx.y == 1) ? gQ : gV;
    float4 a = *(const float4*)(src + i);
    float4 b = *(const float4*)(src + i + 4);
    *(uint4*)(dst + i) = make_uint4(pkh2(a.x * sc, a.y * sc), pkh2(a.z * sc, a.w * sc),
                                    pkh2(b.x * sc, b.y * sc), pkh2(b.z * sc, b.w * sc));
}

// ---- kernel 2: attention ----
__global__ __launch_bounds__(256, 2)
void attn_mma_v6(float* __restrict__ Out)
{
    extern __shared__ char smem[];
    const uint32_t sb = smem_u32(smem);
    const int tid  = threadIdx.x;
    const int wid  = tid >> 5, lane = tid & 31;
    const int g    = lane >> 2, tig = lane & 3;
    const int nw0  = wid * 16;
    const int b    = blockIdx.y, n0 = blockIdx.x * 128;
    const size_t base = (size_t)b * CD * NSEQ;
    const __half* kh = gK + base;
    const __half* qh = gQ + base;
    const __half* vh = gV + base;

    const int cc = tid >> 4, jc = tid & 15;

    // ---- prologue: K tile + tile 0 of Q/V ----
    #pragma unroll
    for (int i = 0; i < 4; ++i) {
        int c = cc + i * 16;
        CP16(sb + OFF_KS + c * STR + jc * 16, kh + (size_t)c * NSEQ + n0 + jc * 8);
        CP16(sb + OFF_Q0 + c * STR + jc * 16, qh + (size_t)c * NSEQ + jc * 8);
        CP16(sb + OFF_V0 + c * STR + jc * 16, vh + (size_t)c * NSEQ + jc * 8);
    }
    CP_COMMIT();

    float o[8][4];
    float ors[4];                       // rowsum accumulator (ones-column MMA)
    #pragma unroll
    for (int e = 0; e < 4; ++e) ors[e] = 0.f;
    #pragma unroll
    for (int oc = 0; oc < 8; ++oc)
        #pragma unroll
        for (int e = 0; e < 4; ++e) o[oc][e] = 0.f;

    const uint32_t kaddr = sb + OFF_KS + ((lane & 7) + ((lane & 16) ? 8 : 0)) * STR
                         + (nw0 + ((lane & 8) ? 8 : 0)) * 2;
    const uint32_t qbase = ((lane & 7) + ((lane & 8) ? 8 : 0)) * STR
                         + ((lane & 16) ? 16 : 0);
    const uint32_t vbase = ((lane & 7) + ((lane & 16) ? 8 : 0)) * STR
                         + ((lane & 8) ? 16 : 0);

    CP_WAIT0();
    __syncthreads();

    // K fragments: constant across all tiles
    uint32_t ak[4][4];
    #pragma unroll
    for (int kk = 0; kk < 4; ++kk)
        LDSM4T(ak[kk][0], ak[kk][1], ak[kk][2], ak[kk][3], kaddr + kk * 16 * STR);

    for (int t = 0; t < 32; ++t) {
        const uint32_t qs = sb + ((t & 1) ? OFF_Q1 : OFF_Q0);
        const uint32_t vs = sb + ((t & 1) ? OFF_V1 : OFF_V0);

        if (t > 0) { CP_WAIT0(); __syncthreads(); }

        if (t + 1 < 32) {
            const uint32_t qo = (t & 1) ? OFF_Q0 : OFF_Q1;
            const uint32_t vo = (t & 1) ? OFF_V0 : OFF_V1;
            const __half* qsrc = qh + (size_t)(t + 1) * 128;
            const __half* vsrc = vh + (size_t)(t + 1) * 128;
            #pragma unroll
            for (int i = 0; i < 4; ++i) {
                int c = cc + i * 16;
                CP16(sb + qo + c * STR + jc * 16, qsrc + (size_t)c * NSEQ + jc * 8);
                CP16(sb + vo + c * STR + jc * 16, vsrc + (size_t)c * NSEQ + jc * 8);
            }
            CP_COMMIT();
        }

        #pragma unroll
        for (int h = 0; h < 2; ++h) {
            const uint32_t hoff = h * 128;

            // ---- GEMM1: S[16n][64m] = (c*K)^T x Q (log2-domain scores) ----
            float s[8][4];
            #pragma unroll
            for (int mt = 0; mt < 8; ++mt)
                #pragma unroll
                for (int e = 0; e < 4; ++e) s[mt][e] = 0.f;

            #pragma unroll
            for (int mp = 0; mp < 4; ++mp)
                #pragma unroll
                for (int kk = 0; kk < 4; ++kk) {
                    uint32_t b0, b1, b2, b3;
                    LDSM4T(b0, b1, b2, b3, qs + qbase + kk * 16 * STR + hoff + mp * 32);
                    MMA16(s[2 * mp],     ak[kk][0], ak[kk][1], ak[kk][2], ak[kk][3], b0, b1);
                    MMA16(s[2 * mp + 1], ak[kk][0], ak[kk][1], ak[kk][2], ak[kk][3], b2, b3);
                }

            // ---- GEMM2: P = 2^S via pkh2 + ex2.f16x2, fused with O += P x V^T
            //      and rowsum += P x ones ----
            #pragma unroll
            for (int kk = 0; kk < 4; ++kk) {
                uint32_t a0 = ex2h2(pkh2(s[2 * kk][0],     s[2 * kk][1]));
                uint32_t a1 = ex2h2(pkh2(s[2 * kk][2],     s[2 * kk][3]));
                uint32_t a2 = ex2h2(pkh2(s[2 * kk + 1][0], s[2 * kk + 1][1]));
                uint32_t a3 = ex2h2(pkh2(s[2 * kk + 1][2], s[2 * kk + 1][3]));
                MMA16(ors, a0, a1, a2, a3, ONES2, ONES2);   // denominator
                #pragma unroll
                for (int ct = 0; ct < 4; ++ct) {
                    uint32_t b0, b1, b2, b3;
                    LDSM4(b0, b1, b2, b3, vs + vbase + ct * 16 * STR + hoff + kk * 32);
                    MMA16(o[2 * ct],     a0, a1, a2, a3, b0, b1);
                    MMA16(o[2 * ct + 1], a0, a1, a2, a3, b2, b3);
                }
            }
        }
    }

    // every lane holds its own rows' sums: ors[0] = row g, ors[2] = row g+8
    const float inv0 = 1.f / ors[0];
    const float inv1 = 1.f / ors[2];

    __syncthreads();   // smem tiles dead -> O staging

    #pragma unroll
    for (int oc = 0; oc < 8; ++oc)
        #pragma unroll
        for (int e = 0; e < 4; ++e) {
            int c = 8 * oc + 2 * tig + (e & 1);
            int n = nw0 + g + 8 * (e >> 1);
            *(float*)(smem + c * OSTB + n * 4) = o[oc][e] * ((e < 2) ? inv0 : inv1);
        }
    __syncthreads();

    #pragma unroll
    for (int i = 0; i < 32; ++i) {
        int flat = i * 256 + tid;
        int c = flat >> 7, n = flat & 127;
        Out[base + (size_t)c * NSEQ + n0 + n] = *(const float*)(smem + c * OSTB + n * 4);
    }
}

extern "C" void kernel_launch(void* const* d_in, const int* in_sizes, int n_in,
                              void* d_out, int out_size)
{
    const float* k = (const float*)d_in[0];
    const float* q = (const float*)d_in[1];
    const float* v = (const float*)d_in[2];
    float* out = (float*)d_out;

    dim3 gcvt(TOT / (256 * 8), 3);
    cvt_to_f16<<<gcvt, 256>>>(k, q, v);

    cudaFuncSetAttribute(attn_mma_v6, cudaFuncAttributeMaxDynamicSharedMemorySize, SMEM_TOTAL);
    dim3 grid(NSEQ / 128, 8);
    attn_mma_v6<<<grid, 256, SMEM_TOTAL>>>(out);
}

// round 10
// speedup vs baseline: 1.6772x; 1.1094x over previous
#include <cuda_runtime.h>
#include <cuda_fp16.h>
#include <cstdint>
#include <math.h>

// SelfAttention B=8, C=64, N=4096 fp32. v7:
//  - fp16 m16n8k16 + ldmatrix, pre-converted fp16 globals (K pre-scaled by
//    0.125*log2e), softmax via pkh2+ex2.f16x2, rowsum via ones-column MMA.
//  - NEW: 32 n-rows per warp (2 A blocks) -> every Q/V B-fragment feeds 4 MMAs
//    (smem bytes/MMA halved; smem no longer co-binding with the HMMA pipe).
//    CTA = 256 thr = 8 warps x 32n = 256 n-rows. 1 CTA/SM, <=255 regs.
//  - 3-stage cp.async ring, wait_group(1): barrier waits on 2-tile-old load.

#define NSEQ 4096
#define CD   64
#define TOT  (8 * CD * NSEQ)

#define KSB  528               // K row stride bytes (256 n * 2B + 16)
#define STR  272               // Q/V row stride bytes (128 m * 2B + 16)
#define OFF_KS 0               // K [c=64][n=256] fp16, 33792 B
#define STG0   33792           // 3 stages, each Q(17408)+V(17408)
#define STGSZ  34816
#define STGV   17408
#define SMEM_TOTAL 138240
#define OSTB   1040            // epilogue fp32 O staging stride (offset 0)

#define ONES2 0x3C003C00u      // f16x2 {1.0, 1.0}

__device__ __align__(16) __half gK[TOT];
__device__ __align__(16) __half gQ[TOT];
__device__ __align__(16) __half gV[TOT];

static __device__ __forceinline__ uint32_t smem_u32(const void* p) {
    uint32_t a;
    asm("{ .reg .u64 t; cvta.to.shared.u64 t, %1; cvt.u32.u64 %0, t; }" : "=r"(a) : "l"(p));
    return a;
}
static __device__ __forceinline__ uint32_t pkh2(float lo, float hi) {
    uint32_t d;
    asm("cvt.rn.f16x2.f32 %0, %1, %2;" : "=r"(d) : "f"(hi), "f"(lo));
    return d;
}
static __device__ __forceinline__ uint32_t ex2h2(uint32_t x) {
    uint32_t d;
    asm("ex2.approx.f16x2 %0, %1;" : "=r"(d) : "r"(x));
    return d;
}

#define CP16(dst, src) asm volatile("cp.async.cg.shared.global [%0], [%1], 16;" :: "r"(dst), "l"(src) : "memory")
#define CP_COMMIT()    asm volatile("cp.async.commit_group;" ::: "memory")
#define CP_WAIT(n)     asm volatile("cp.async.wait_group %0;" :: "n"(n) : "memory")

#define LDSM4(r0,r1,r2,r3,a) \
    asm volatile("ldmatrix.sync.aligned.m8n8.x4.shared.b16 {%0,%1,%2,%3}, [%4];" \
        : "=r"(r0),"=r"(r1),"=r"(r2),"=r"(r3) : "r"(a))
#define LDSM4T(r0,r1,r2,r3,a) \
    asm volatile("ldmatrix.sync.aligned.m8n8.x4.trans.shared.b16 {%0,%1,%2,%3}, [%4];" \
        : "=r"(r0),"=r"(r1),"=r"(r2),"=r"(r3) : "r"(a))

#define MMA16(d, a0, a1, a2, a3, b0, b1)                                         \
    asm volatile("mma.sync.aligned.m16n8k16.row.col.f32.f16.f16.f32 "            \
        "{%0,%1,%2,%3}, {%4,%5,%6,%7}, {%8,%9}, {%0,%1,%2,%3};"                  \
        : "+f"((d)[0]), "+f"((d)[1]), "+f"((d)[2]), "+f"((d)[3])                 \
        : "r"(a0), "r"(a1), "r"(a2), "r"(a3), "r"(b0), "r"(b1))

// ---- kernel 1: fp32 -> fp16 (K pre-scaled by 0.125*log2 e) ----
__global__ __launch_bounds__(256)
void cvt_to_f16(const float* __restrict__ K, const float* __restrict__ Q,
                const float* __restrict__ V)
{
    const int i = (blockIdx.x * 256 + threadIdx.x) * 8;
    const float sc = (blockIdx.y == 0) ? 0.18033688011112042f : 1.0f;
    const float* src = (blockIdx.y == 0) ? K : (blockIdx.y == 1) ? Q : V;
    __half* dst = (blockIdx.y == 0) ? gK : (blockIdx.y == 1) ? gQ : gV;
    float4 a = *(const float4*)(src + i);
    float4 b = *(const float4*)(src + i + 4);
    *(uint4*)(dst + i) = make_uint4(pkh2(a.x * sc, a.y * sc), pkh2(a.z * sc, a.w * sc),
                                    pkh2(b.x * sc, b.y * sc), pkh2(b.z * sc, b.w * sc));
}

// ---- kernel 2: attention ----
__global__ __launch_bounds__(256, 1)
void attn_mma_v7(float* __restrict__ Out)
{
    extern __shared__ char smem[];
    const uint32_t sb = smem_u32(smem);
    const int tid  = threadIdx.x;
    const int wid  = tid >> 5, lane = tid & 31;
    const int g    = lane >> 2, tig = lane & 3;
    const int nw0  = wid * 32;                  // warp's 32-row block in CTA
    const int b    = blockIdx.y, n0 = blockIdx.x * 256;
    const size_t base = (size_t)b * CD * NSEQ;
    const __half* kh = gK + base;
    const __half* qh = gQ + base;
    const __half* vh = gV + base;

    const int cc = tid >> 4, jc = tid & 15;     // Q/V loader lanes

    // ---- prologue group 0: K tile [c=64][n=256] + tile 0 Q/V ----
    #pragma unroll
    for (int i = 0; i < 8; ++i) {
        int flat = i * 256 + tid, c = flat >> 5, j = flat & 31;
        CP16(sb + OFF_KS + c * KSB + j * 16, kh + (size_t)c * NSEQ + n0 + j * 8);
    }
    #pragma unroll
    for (int i = 0; i < 4; ++i) {
        int c = cc + i * 16;
        CP16(sb + STG0 + c * STR + jc * 16, qh + (size_t)c * NSEQ + jc * 8);
        CP16(sb + STG0 + STGV + c * STR + jc * 16, vh + (size_t)c * NSEQ + jc * 8);
    }
    CP_COMMIT();
    // group 1: tile 1
    #pragma unroll
    for (int i = 0; i < 4; ++i) {
        int c = cc + i * 16;
        CP16(sb + STG0 + STGSZ + c * STR + jc * 16, qh + (size_t)c * NSEQ + 128 + jc * 8);
        CP16(sb + STG0 + STGSZ + STGV + c * STR + jc * 16, vh + (size_t)c * NSEQ + 128 + jc * 8);
    }
    CP_COMMIT();

    float o[2][8][4];                // O: [nblk][ct][frag]
    float ors[2][4];                 // rowsum via ones-MMA: [nblk][frag]
    #pragma unroll
    for (int nb = 0; nb < 2; ++nb) {
        #pragma unroll
        for (int e = 0; e < 4; ++e) ors[nb][e] = 0.f;
        #pragma unroll
        for (int ct = 0; ct < 8; ++ct)
            #pragma unroll
            for (int e = 0; e < 4; ++e) o[nb][ct][e] = 0.f;
    }

    const uint32_t kaddr = sb + OFF_KS + ((lane & 7) + ((lane & 16) ? 8 : 0)) * KSB
                         + (nw0 + ((lane & 8) ? 8 : 0)) * 2;
    const uint32_t qbase = ((lane & 7) + ((lane & 8) ? 8 : 0)) * STR
                         + ((lane & 16) ? 16 : 0);
    const uint32_t vbase = ((lane & 7) + ((lane & 16) ? 8 : 0)) * STR
                         + ((lane & 8) ? 16 : 0);

    CP_WAIT(1);            // group 0 (K + tile 0) done
    __syncthreads();

    // K A-fragments: [nblk][kk][4], constant across all tiles (32 regs)
    uint32_t ak[2][4][4];
    #pragma unroll
    for (int nb = 0; nb < 2; ++nb)
        #pragma unroll
        for (int kk = 0; kk < 4; ++kk)
            LDSM4T(ak[nb][kk][0], ak[nb][kk][1], ak[nb][kk][2], ak[nb][kk][3],
                   kaddr + nb * 32 + kk * 16 * KSB);

    for (int t = 0; t < 32; ++t) {
        const uint32_t stg = sb + STG0 + (uint32_t)(t % 3) * STGSZ;
        const uint32_t qs = stg, vs = stg + STGV;

        if (t > 0) { CP_WAIT(1); __syncthreads(); }   // tile t ready (t+1 in flight)

        if (t + 2 < 32) {            // prefetch tile t+2 into stage (t+2)%3
            const uint32_t so = sb + STG0 + (uint32_t)((t + 2) % 3) * STGSZ;
            const __half* qsrc = qh + (size_t)(t + 2) * 128;
            const __half* vsrc = vh + (size_t)(t + 2) * 128;
            #pragma unroll
            for (int i = 0; i < 4; ++i) {
                int c = cc + i * 16;
                CP16(so + c * STR + jc * 16, qsrc + (size_t)c * NSEQ + jc * 8);
                CP16(so + STGV + c * STR + jc * 16, vsrc + (size_t)c * NSEQ + jc * 8);
            }
            CP_COMMIT();
        }

        #pragma unroll
        for (int h = 0; h < 2; ++h) {
            const uint32_t hoff = h * 128;

            // ---- GEMM1: S[32n][64m] = (c*K)^T x Q ----
            float s[2][8][4];
            #pragma unroll
            for (int nb = 0; nb < 2; ++nb)
                #pragma unroll
                for (int mt = 0; mt < 8; ++mt)
                    #pragma unroll
                    for (int e = 0; e < 4; ++e) s[nb][mt][e] = 0.f;

            #pragma unroll
            for (int mp = 0; mp < 4; ++mp)
                #pragma unroll
                for (int kk = 0; kk < 4; ++kk) {
                    uint32_t b0, b1, b2, b3;
                    LDSM4T(b0, b1, b2, b3, qs + qbase + kk * 16 * STR + hoff + mp * 32);
                    #pragma unroll
                    for (int nb = 0; nb < 2; ++nb) {
                        MMA16(s[nb][2 * mp],     ak[nb][kk][0], ak[nb][kk][1], ak[nb][kk][2], ak[nb][kk][3], b0, b1);
                        MMA16(s[nb][2 * mp + 1], ak[nb][kk][0], ak[nb][kk][1], ak[nb][kk][2], ak[nb][kk][3], b2, b3);
                    }
                }

            // ---- P = 2^S (pkh2 + ex2.f16x2); O += P x V^T; rowsum += P x 1 ----
            #pragma unroll
            for (int kk = 0; kk < 4; ++kk) {
                uint32_t a[2][4];
                #pragma unroll
                for (int nb = 0; nb < 2; ++nb) {
                    a[nb][0] = ex2h2(pkh2(s[nb][2 * kk][0],     s[nb][2 * kk][1]));
                    a[nb][1] = ex2h2(pkh2(s[nb][2 * kk][2],     s[nb][2 * kk][3]));
                    a[nb][2] = ex2h2(pkh2(s[nb][2 * kk + 1][0], s[nb][2 * kk + 1][1]));
                    a[nb][3] = ex2h2(pkh2(s[nb][2 * kk + 1][2], s[nb][2 * kk + 1][3]));
                    MMA16(ors[nb], a[nb][0], a[nb][1], a[nb][2], a[nb][3], ONES2, ONES2);
                }
                #pragma unroll
                for (int ct = 0; ct < 4; ++ct) {
                    uint32_t b0, b1, b2, b3;
                    LDSM4(b0, b1, b2, b3, vs + vbase + ct * 16 * STR + hoff + kk * 32);
                    #pragma unroll
                    for (int nb = 0; nb < 2; ++nb) {
                        MMA16(o[nb][2 * ct],     a[nb][0], a[nb][1], a[nb][2], a[nb][3], b0, b1);
                        MMA16(o[nb][2 * ct + 1], a[nb][0], a[nb][1], a[nb][2], a[nb][3], b2, b3);
                    }
                }
            }
        }
    }

    // per-lane row sums: ors[nb][0] = row nw0+nb*16+g, ors[nb][2] = +8
    float inv[2][2];
    #pragma unroll
    for (int nb = 0; nb < 2; ++nb) {
        inv[nb][0] = 1.f / ors[nb][0];
        inv[nb][1] = 1.f / ors[nb][2];
    }

    __syncthreads();   // tile smem dead -> O staging [c=64][n=256] stride OSTB

    #pragma unroll
    for (int nb = 0; nb < 2; ++nb)
        #pragma unroll
        for (int ct = 0; ct < 8; ++ct)
            #pragma unroll
            for (int e = 0; e < 4; ++e) {
                int c = 8 * ct + 2 * tig + (e & 1);
                int n = nw0 + nb * 16 + g + 8 * (e >> 1);
                *(float*)(smem + c * OSTB + n * 4) = o[nb][ct][e] * inv[nb][e >> 1];
            }
    __syncthreads();

    // coalesced vectorized store: 64 c-rows x 64 float4
    #pragma unroll
    for (int i = 0; i < 16; ++i) {
        int flat = i * 256 + tid;
        int c = flat >> 6, nq = flat & 63;
        float4 v = *(const float4*)(smem + c * OSTB + nq * 16);
        *(float4*)(Out + base + (size_t)c * NSEQ + n0 + nq * 4) = v;
    }
}

extern "C" void kernel_launch(void* const* d_in, const int* in_sizes, int n_in,
                              void* d_out, int out_size)
{
    const float* k = (const float*)d_in[0];
    const float* q = (const float*)d_in[1];
    const float* v = (const float*)d_in[2];
    float* out = (float*)d_out;

    dim3 gcvt(TOT / (256 * 8), 3);
    cvt_to_f16<<<gcvt, 256>>>(k, q, v);

    cudaFuncSetAttribute(attn_mma_v7, cudaFuncAttributeMaxDynamicSharedMemorySize, SMEM_TOTAL);
    dim3 grid(NSEQ / 256, 8);          // 16 x 8 = 128 CTAs, 1 per SM
    attn_mma_v7<<<grid, 256, SMEM_TOTAL>>>(out);
}